// round 5
// baseline (speedup 1.0000x reference)
#include <cuda_runtime.h>
#include <math.h>
#include <stdint.h>

#define TT 64
#define BB 128
#define NN 256
#define DD 300
#define HD 300
#define GG 1200
#define LL 20
#define ML 320
#define EPSF 1e-8f

// ---------------- device scratch (no allocations allowed) ----------------
static __device__ float g_comb[TT*NN*DD];     // (T,256,300)
static __device__ float g_Xg[TT*NN*GG];       // precomputed x@Wih^T+b  (T,256,1200)
static __device__ float g_hsf[TT*NN*HD];
static __device__ float g_hsb[TT*NN*HD];
static __device__ float g_cf[NN*HD];
static __device__ float g_cb[NN*HD];
static __device__ float g_m[TT*BB*ML];        // matching output (T,128,320)
static __device__ float g_aXf[TT*BB*GG];
static __device__ float g_aXb[TT*BB*GG];
static __device__ float g_ahf[2*BB*HD];
static __device__ float g_ahb[2*BB*HD];
static __device__ float g_acf[BB*HD];
static __device__ float g_acb[BB*HD];
static __device__ float g_w[BB*TT*TT];        // attention weights [b][t][s]
static __device__ int   g_idx[BB*TT];         // argmax index [b][t]
static __device__ float g_Pl2[TT*BB];
static __device__ float g_Hl2[TT*BB];
static __device__ float g_hmean[TT*BB*HD];    // (t,b,h)
static __device__ float g_pnm[TT*BB*LL];
static __device__ float g_hnm[TT*BB*LL];
static __device__ float g_y1[BB*600];
static __device__ float g_y2[BB*600];

// ---------------- fast math helpers ----------------
__device__ __forceinline__ float sigmf(float x) {
    return __fdividef(1.f, 1.f + __expf(-x));
}
__device__ __forceinline__ float tanh_fast(float x) {
    float t = __expf(-2.f * fabsf(x));
    float y = __fdividef(1.f - t, 1.f + t);
    return copysignf(y, x);
}
__device__ __forceinline__ uint32_t f2tf32(float v) {
    uint32_t o; asm("cvt.rna.tf32.f32 %0, %1;" : "=r"(o) : "f"(v)); return o;
}
// split v into tf32 hi + tf32 lo (3xTF32 recipe)
__device__ __forceinline__ void tf32_split(float v, uint32_t& hi, uint32_t& lo) {
    hi = f2tf32(v);
    lo = f2tf32(v - __uint_as_float(hi));
}
__device__ __forceinline__ void mma8(float* d,
                                     uint32_t a0, uint32_t a1, uint32_t a2, uint32_t a3,
                                     uint32_t b0, uint32_t b1) {
    asm volatile("mma.sync.aligned.m16n8k8.row.col.f32.tf32.tf32.f32 "
        "{%0,%1,%2,%3}, {%4,%5,%6,%7}, {%8,%9}, {%0,%1,%2,%3};"
        : "+f"(d[0]), "+f"(d[1]), "+f"(d[2]), "+f"(d[3])
        : "r"(a0), "r"(a1), "r"(a2), "r"(a3), "r"(b0), "r"(b1));
}

// ---------------- kernels ----------------

__global__ void embed_kernel(const int* __restrict__ prem, const int* __restrict__ hyp,
                             const float* __restrict__ E, float* __restrict__ comb)
{
    int i = blockIdx.x * 256 + threadIdx.x;
    if (i >= TT*NN*DD) return;
    int d = i % DD;
    int n = (i / DD) % NN;
    int t = i / (DD*NN);
    int tok = (n < BB) ? prem[t*BB + n] : hyp[t*BB + n - BB];
    comb[i] = E[(size_t)tok*DD + d];
}

// ===== 3xTF32 tensor-core GEMM:  C[M,N] = A[M,K] @ Bw[N,K]^T + bias[N]  =====
// Block tile 64x64, 128 threads = 4 warps in m32n32 quadrants, KT=32 (4 k8 mma steps).
// smem holds fp32; hi/lo tf32 split happens at fragment load (amortized over mmas).
__global__ void gemm_nt_3tf32(const float* __restrict__ A, const float* __restrict__ Bw,
                              const float* __restrict__ bias, float* __restrict__ C,
                              int M, int N, int K)
{
    __shared__ float sA[64*36];
    __shared__ float sB[64*36];
    int n0 = blockIdx.x * 64, m0 = blockIdx.y * 64;
    int tid = threadIdx.x;
    int warp = tid >> 5, lane = tid & 31;
    int mh = warp >> 1, nh = warp & 1;
    int g = lane >> 2, t = lane & 3;
    float acc[2][4][4] = {};
    int nkt = (K + 31) / 32;

    for (int kt = 0; kt < nkt; kt++) {
        int k0 = kt * 32;
        __syncthreads();
        for (int i = tid; i < 64*32; i += 128) {
            int r = i >> 5, c = i & 31;
            int k = k0 + c;
            sA[r*36 + c] = (k < K) ? A[(size_t)(m0 + r)*K + k] : 0.f;
        }
        for (int i = tid; i < 64*32; i += 128) {
            int r = i >> 5, c = i & 31;
            int k = k0 + c; int nn = n0 + r;
            sB[r*36 + c] = (nn < N && k < K) ? Bw[(size_t)nn*K + k] : 0.f;
        }
        __syncthreads();
        #pragma unroll
        for (int k8 = 0; k8 < 4; k8++) {
            int kk = k8 * 8;
            uint32_t ah[2][4], al[2][4], bh[4][2], bl[4][2];
            #pragma unroll
            for (int mt = 0; mt < 2; mt++) {
                int rb = mh*32 + mt*16;
                tf32_split(sA[(rb + g)*36 + kk + t],       ah[mt][0], al[mt][0]);
                tf32_split(sA[(rb + g + 8)*36 + kk + t],   ah[mt][1], al[mt][1]);
                tf32_split(sA[(rb + g)*36 + kk + t + 4],   ah[mt][2], al[mt][2]);
                tf32_split(sA[(rb + g + 8)*36 + kk + t + 4], ah[mt][3], al[mt][3]);
            }
            #pragma unroll
            for (int nt = 0; nt < 4; nt++) {
                int nb = nh*32 + nt*8;
                tf32_split(sB[(nb + g)*36 + kk + t],     bh[nt][0], bl[nt][0]);
                tf32_split(sB[(nb + g)*36 + kk + t + 4], bh[nt][1], bl[nt][1]);
            }
            #pragma unroll
            for (int mt = 0; mt < 2; mt++)
                #pragma unroll
                for (int nt = 0; nt < 4; nt++) {
                    mma8(acc[mt][nt], ah[mt][0], ah[mt][1], ah[mt][2], ah[mt][3],
                         bl[nt][0], bl[nt][1]);
                    mma8(acc[mt][nt], al[mt][0], al[mt][1], al[mt][2], al[mt][3],
                         bh[nt][0], bh[nt][1]);
                    mma8(acc[mt][nt], ah[mt][0], ah[mt][1], ah[mt][2], ah[mt][3],
                         bh[nt][0], bh[nt][1]);
                }
        }
    }
    #pragma unroll
    for (int mt = 0; mt < 2; mt++) {
        int r = m0 + mh*32 + mt*16 + g;
        #pragma unroll
        for (int nt = 0; nt < 4; nt++) {
            int c = n0 + nh*32 + nt*8 + 2*t;
            if (c < N) {
                float bv = bias[c];
                C[(size_t)r*N + c]       = acc[mt][nt][0] + bv;
                C[(size_t)(r + 8)*N + c] = acc[mt][nt][2] + bv;
            }
            if (c + 1 < N) {
                float bv = bias[c + 1];
                C[(size_t)r*N + c + 1]       = acc[mt][nt][1] + bv;
                C[(size_t)(r + 8)*N + c + 1] = acc[mt][nt][3] + bv;
            }
        }
    }
}

// ===== 3xTF32 maxp: one block per batch b, P/H resident in smem, loop over all 20 l =====
// maxp[t,b,l] = max_s  (sum_h P[t,h]*W2[l,h]*H[s,h]) / (pn[t,b,l]*hn[s,b,l] + eps)
#define MAXP_SMEM_FLOATS (64*308*2 + 320 + 64 + 64 + 128)
__global__ void maxp_3tf32_kernel(const float* __restrict__ P, const float* __restrict__ Hm,
                                  const float* __restrict__ Wm,
                                  const float* __restrict__ pnm, const float* __restrict__ hnm,
                                  float* __restrict__ mout, int moff)
{
    extern __shared__ float sm[];
    float* sP   = sm;                  // [64][308] fp32
    float* sH   = sm + 64*308;         // [64][308] fp32
    float* sW2  = sH + 64*308;         // [320]
    float* sPN  = sW2 + 320;           // [64]
    float* sHN  = sPN + 64;            // [64]
    float* sRed = sHN + 64;            // [64][2]

    int b = blockIdx.x;
    int tid = threadIdx.x;
    const int TS = NN*HD;
    int warp = tid >> 5, lane = tid & 31;
    int mh = warp >> 1, nh = warp & 1;
    int g = lane >> 2, t = lane & 3;

    for (int i = tid; i < 64*308; i += 128) {
        int r = i / 308, k = i % 308;
        sP[i] = (k < HD) ? P [(size_t)r*TS + b*HD + k] : 0.f;
        sH[i] = (k < HD) ? Hm[(size_t)r*TS + b*HD + k] : 0.f;
    }

    for (int l = 0; l < LL; l++) {
        __syncthreads();
        for (int k = tid; k < 308; k += 128) {
            float w = (k < HD) ? Wm[l*HD + k] : 0.f;
            sW2[k] = w * w;
        }
        if (tid < 64)       sPN[tid]      = pnm[(tid*BB + b)*LL + l];
        else if (tid < 128) sHN[tid - 64] = hnm[((tid - 64)*BB + b)*LL + l];
        __syncthreads();

        float acc[2][4][4] = {};
        for (int k8i = 0; k8i < 38; k8i++) {
            int kk = k8i * 8;
            float wA = sW2[kk + t], wB = sW2[kk + t + 4];
            uint32_t ah[2][4], al[2][4], bh[4][2], bl[4][2];
            #pragma unroll
            for (int mt = 0; mt < 2; mt++) {
                int rb = mh*32 + mt*16;
                tf32_split(sP[(rb + g)*308 + kk + t] * wA,       ah[mt][0], al[mt][0]);
                tf32_split(sP[(rb + g + 8)*308 + kk + t] * wA,   ah[mt][1], al[mt][1]);
                tf32_split(sP[(rb + g)*308 + kk + t + 4] * wB,   ah[mt][2], al[mt][2]);
                tf32_split(sP[(rb + g + 8)*308 + kk + t + 4] * wB, ah[mt][3], al[mt][3]);
            }
            #pragma unroll
            for (int nt = 0; nt < 4; nt++) {
                int nb = nh*32 + nt*8;
                tf32_split(sH[(nb + g)*308 + kk + t],     bh[nt][0], bl[nt][0]);
                tf32_split(sH[(nb + g)*308 + kk + t + 4], bh[nt][1], bl[nt][1]);
            }
            #pragma unroll
            for (int mt = 0; mt < 2; mt++)
                #pragma unroll
                for (int nt = 0; nt < 4; nt++) {
                    mma8(acc[mt][nt], ah[mt][0], ah[mt][1], ah[mt][2], ah[mt][3],
                         bl[nt][0], bl[nt][1]);
                    mma8(acc[mt][nt], al[mt][0], al[mt][1], al[mt][2], al[mt][3],
                         bh[nt][0], bh[nt][1]);
                    mma8(acc[mt][nt], ah[mt][0], ah[mt][1], ah[mt][2], ah[mt][3],
                         bh[nt][0], bh[nt][1]);
                }
        }

        // epilogue: v = acc/(pn*hn+eps), max over s (cols)
        float rowmax[2][2];
        #pragma unroll
        for (int mt = 0; mt < 2; mt++) {
            int r0 = mh*32 + mt*16 + g;
            float pn0 = sPN[r0], pn1 = sPN[r0 + 8];
            float m0v = -1e30f, m1v = -1e30f;
            #pragma unroll
            for (int nt = 0; nt < 4; nt++) {
                int c0 = nh*32 + nt*8 + 2*t;
                float hn0 = sHN[c0], hn1 = sHN[c0 + 1];
                m0v = fmaxf(m0v, acc[mt][nt][0] / (pn0*hn0 + EPSF));
                m0v = fmaxf(m0v, acc[mt][nt][1] / (pn0*hn1 + EPSF));
                m1v = fmaxf(m1v, acc[mt][nt][2] / (pn1*hn0 + EPSF));
                m1v = fmaxf(m1v, acc[mt][nt][3] / (pn1*hn1 + EPSF));
            }
            #pragma unroll
            for (int o = 1; o < 4; o <<= 1) {
                m0v = fmaxf(m0v, __shfl_xor_sync(0xffffffffu, m0v, o));
                m1v = fmaxf(m1v, __shfl_xor_sync(0xffffffffu, m1v, o));
            }
            rowmax[mt][0] = m0v; rowmax[mt][1] = m1v;
        }
        if (t == 0) {
            #pragma unroll
            for (int mt = 0; mt < 2; mt++) {
                int r0 = mh*32 + mt*16 + g;
                sRed[r0*2 + nh]       = rowmax[mt][0];
                sRed[(r0 + 8)*2 + nh] = rowmax[mt][1];
            }
        }
        __syncthreads();
        if (tid < 64) {
            float v = fmaxf(sRed[tid*2], sRed[tid*2 + 1]);
            mout[((size_t)tid*BB + b)*ML + moff + 20 + l] = v;
        }
    }
}

// One LSTM timestep, both directions (blockIdx.z). Block tile: RT rows x 16 j x 4 gates.
template<int RT>
__global__ void lstm_step2(
    const float* __restrict__ xg_f, const float* __restrict__ xg_b,
    const float* __restrict__ Whh_f, const float* __restrict__ Whh_b,
    const float* __restrict__ hp_f, const float* __restrict__ hp_b,
    float* __restrict__ ho_f, float* __restrict__ ho_b,
    float* __restrict__ c_f, float* __restrict__ c_b,
    int first)
{
    constexpr int NT = 4 * RT;
    constexpr int NH = (30*RT + NT - 1) / NT;
    constexpr int NW = (30*64 + NT - 1) / NT;

    int dir = blockIdx.z;
    const float* xg  = dir ? xg_b  : xg_f;
    const float* Whh = dir ? Whh_b : Whh_f;
    const float* hp  = dir ? hp_b  : hp_f;
    float* ho = dir ? ho_b : ho_f;
    float* cs = dir ? c_b  : c_f;

    int j0 = blockIdx.x * 16;
    int r0 = blockIdx.y * RT;
    int tx = threadIdx.x;
    int ty = threadIdx.y;
    int tid = ty * 16 + tx;

    __shared__ __align__(16) float sH[30][RT + 4];
    __shared__ __align__(16) float sW[30][68];
    float acc[4][4] = {};

    if (!first) {
        float hA[NH], hW[NW];
        #pragma unroll
        for (int u = 0; u < NH; u++) {
            int i = tid + u*NT;
            if (i < 30*RT) { int r = i/30, c = i%30; hA[u] = hp[(size_t)(r0 + r)*HD + c]; }
        }
        #pragma unroll
        for (int u = 0; u < NW; u++) {
            int i = tid + u*NT;
            if (i < 30*64) {
                int rr = i/30, c = i%30;
                int gg = rr & 3, jl = rr >> 2;
                int jj = j0 + jl; if (jj >= HD) jj = HD - 1;
                hW[u] = Whh[(size_t)(gg*HD + jj)*HD + c];
            }
        }
        for (int kt = 0; kt < 10; kt++) {
            #pragma unroll
            for (int u = 0; u < NH; u++) {
                int i = tid + u*NT;
                if (i < 30*RT) { int r = i/30, c = i%30; sH[c][r] = hA[u]; }
            }
            #pragma unroll
            for (int u = 0; u < NW; u++) {
                int i = tid + u*NT;
                if (i < 30*64) { int rr = i/30, c = i%30; sW[c][rr] = hW[u]; }
            }
            __syncthreads();
            if (kt < 9) {
                int k0 = (kt + 1) * 30;
                #pragma unroll
                for (int u = 0; u < NH; u++) {
                    int i = tid + u*NT;
                    if (i < 30*RT) { int r = i/30, c = i%30; hA[u] = hp[(size_t)(r0 + r)*HD + k0 + c]; }
                }
                #pragma unroll
                for (int u = 0; u < NW; u++) {
                    int i = tid + u*NT;
                    if (i < 30*64) {
                        int rr = i/30, c = i%30;
                        int gg = rr & 3, jl = rr >> 2;
                        int jj = j0 + jl; if (jj >= HD) jj = HD - 1;
                        hW[u] = Whh[(size_t)(gg*HD + jj)*HD + k0 + c];
                    }
                }
            }
            #pragma unroll
            for (int k = 0; k < 30; k++) {
                float4 a = *(const float4*)&sH[k][4*ty];
                float4 b = *(const float4*)&sW[k][4*tx];
                acc[0][0] += b.x*a.x; acc[0][1] += b.x*a.y; acc[0][2] += b.x*a.z; acc[0][3] += b.x*a.w;
                acc[1][0] += b.y*a.x; acc[1][1] += b.y*a.y; acc[1][2] += b.y*a.z; acc[1][3] += b.y*a.w;
                acc[2][0] += b.z*a.x; acc[2][1] += b.z*a.y; acc[2][2] += b.z*a.z; acc[2][3] += b.z*a.w;
                acc[3][0] += b.w*a.x; acc[3][1] += b.w*a.y; acc[3][2] += b.w*a.z; acc[3][3] += b.w*a.w;
            }
            __syncthreads();
        }
    }
    int j = j0 + tx;
    if (j < HD) {
        #pragma unroll
        for (int r = 0; r < 4; r++) {
            int row = r0 + 4*ty + r;
            const float* xr = xg + (size_t)row*GG + j;
            float gi = acc[0][r] + xr[0];
            float gf = acc[1][r] + xr[300];
            float gg = acc[2][r] + xr[600];
            float go = acc[3][r] + xr[900];
            float cp = first ? 0.f : cs[row*HD + j];
            float cn = sigmf(gf)*cp + sigmf(gi)*tanh_fast(gg);
            cs[row*HD + j] = cn;
            ho[row*HD + j] = sigmf(go)*tanh_fast(cn);
        }
    }
}

__global__ void l2_kernel(const float* __restrict__ P, const float* __restrict__ Hm,
                          float* __restrict__ Pl2, float* __restrict__ Hl2)
{
    int tb = blockIdx.x;
    int t = tb / BB, b = tb % BB;
    int warp = threadIdx.x >> 5, lane = threadIdx.x & 31;
    const float* row = (warp ? Hm : P) + (size_t)t*NN*HD + b*HD;
    float s = 0.f;
    for (int h = lane; h < HD; h += 32) { float v = row[h]; s += v*v; }
    for (int o = 16; o; o >>= 1) s += __shfl_down_sync(0xffffffffu, s, o);
    if (lane == 0) (warp ? Hl2 : Pl2)[t*BB + b] = sqrtf(s);
}

// Per batch b: att[t,s]=cos(P[t],H[s]); fused row-sum, argmax (first max), writes w.
__global__ void att_kernel(const float* __restrict__ P, const float* __restrict__ Hm,
                           const float* __restrict__ Pl2, const float* __restrict__ Hl2,
                           float* __restrict__ wout, int* __restrict__ idxout)
{
    int b = blockIdx.x;
    __shared__ __align__(16) float sP[20][68], sH[20][68];
    __shared__ float sAtt[64][65];
    __shared__ float sSum[64];
    int tid = threadIdx.x, tx = tid & 15, ty = tid >> 4;
    float acc[4][4] = {};
    const int TS = NN*HD;
    for (int kt = 0; kt < 15; kt++) {
        int k0 = kt*20;
        #pragma unroll
        for (int u = 0; u < 5; u++) {
            int i = tid + u*256;
            int r = i / 20, c = i % 20;
            sP[c][r] = P [(size_t)r*TS + b*HD + k0 + c];
            sH[c][r] = Hm[(size_t)r*TS + b*HD + k0 + c];
        }
        __syncthreads();
        #pragma unroll
        for (int k = 0; k < 20; k++) {
            float4 a = *(const float4*)&sP[k][4*ty];
            float4 bb = *(const float4*)&sH[k][4*tx];
            acc[0][0] += a.x*bb.x; acc[0][1] += a.x*bb.y; acc[0][2] += a.x*bb.z; acc[0][3] += a.x*bb.w;
            acc[1][0] += a.y*bb.x; acc[1][1] += a.y*bb.y; acc[1][2] += a.y*bb.z; acc[1][3] += a.y*bb.w;
            acc[2][0] += a.z*bb.x; acc[2][1] += a.z*bb.y; acc[2][2] += a.z*bb.z; acc[2][3] += a.z*bb.w;
            acc[3][0] += a.w*bb.x; acc[3][1] += a.w*bb.y; acc[3][2] += a.w*bb.z; acc[3][3] += a.w*bb.w;
        }
        __syncthreads();
    }
    #pragma unroll
    for (int i = 0; i < 4; i++) {
        int t = 4*ty + i;
        float pn = Pl2[t*BB + b] + EPSF;
        #pragma unroll
        for (int j = 0; j < 4; j++) {
            int s = 4*tx + j;
            sAtt[t][s] = acc[i][j] / (pn * (Hl2[s*BB + b] + EPSF));
        }
    }
    __syncthreads();
    if (tid < 64) {
        float sum = 0.f, best = -1e30f; int bi = 0;
        for (int s = 0; s < 64; s++) {
            float v = sAtt[tid][s];
            sum += v;
            if (v > best) { best = v; bi = s; }
        }
        sSum[tid] = sum + EPSF;
        idxout[b*64 + tid] = bi;
    }
    __syncthreads();
    for (int i = tid; i < 4096; i += 256) {
        int t = i >> 6;
        wout[b*4096 + i] = sAtt[t][i & 63] / sSum[t];
    }
}

// hmean[t,b,:] = sum_s w[b][t][s] * H[s,b,:]
__global__ void hmean_kernel(const float* __restrict__ Hm, const float* __restrict__ w,
                             float* __restrict__ hmean)
{
    int b = blockIdx.x;
    __shared__ float sW[64][65];
    int tid = threadIdx.x;
    for (int i = tid; i < 4096; i += 256) sW[i >> 6][i & 63] = w[b*4096 + i];
    __syncthreads();
    int tx = tid & 31, ty = tid >> 5;
    const int TS = NN*HD;
    for (int hc = 0; hc < 10; hc++) {
        int h = hc*32 + tx;
        bool valid = h < HD;
        float acc[8] = {};
        for (int s = 0; s < 64; s++) {
            float hv = valid ? Hm[(size_t)s*TS + b*HD + h] : 0.f;
            #pragma unroll
            for (int i = 0; i < 8; i++) acc[i] += sW[ty + 8*i][s] * hv;
        }
        if (valid) {
            #pragma unroll
            for (int i = 0; i < 8; i++) {
                int t = ty + 8*i;
                hmean[((size_t)t*BB + b)*HD + h] = acc[i];
            }
        }
    }
}

// Perspective-weighted norms for the pairwise match
__global__ void pnhn_kernel(const float* __restrict__ P, const float* __restrict__ Hm,
                            const float* __restrict__ Wm,
                            float* __restrict__ pnm, float* __restrict__ hnm)
{
    int tb = blockIdx.x;
    int t = tb / BB, b = tb % BB;
    int warp = threadIdx.x >> 5, lane = threadIdx.x & 31;
    const float* prow = P  + (size_t)t*NN*HD + b*HD;
    const float* hrow = Hm + (size_t)t*NN*HD + b*HD;
    float p2[10], h2[10];
    #pragma unroll
    for (int u = 0; u < 10; u++) {
        int h = lane + 32*u;
        float pv = (h < HD) ? prow[h] : 0.f;
        float hv = (h < HD) ? hrow[h] : 0.f;
        p2[u] = pv*pv; h2[u] = hv*hv;
    }
    for (int l = warp; l < LL; l += 4) {
        float ap = 0.f, ah = 0.f;
        #pragma unroll
        for (int u = 0; u < 10; u++) {
            int h = lane + 32*u;
            float wv = (h < HD) ? Wm[l*HD + h] : 0.f;
            float w2 = wv*wv;
            ap += p2[u]*w2; ah += h2[u]*w2;
        }
        for (int o = 16; o; o >>= 1) {
            ap += __shfl_down_sync(0xffffffffu, ap, o);
            ah += __shfl_down_sync(0xffffffffu, ah, o);
        }
        if (lane == 0) { pnm[tb*LL + l] = sqrtf(ap); hnm[tb*LL + l] = sqrtf(ah); }
    }
}

// full / attm / maxattm fused, one (t,b) per block (4 warps over L)
__global__ void mpcomb_kernel(const float* __restrict__ P, const float* __restrict__ Hm,
                              const float* __restrict__ Vb,
                              const float* __restrict__ hmean,
                              const int* __restrict__ idx,
                              const float* __restrict__ Wf, const float* __restrict__ Wa,
                              const float* __restrict__ Wma,
                              float* __restrict__ mout, int moff)
{
    int tb = blockIdx.x;
    int t = tb / BB, b = tb % BB;
    int warp = threadIdx.x >> 5, lane = threadIdx.x & 31;
    int si = idx[b*64 + t];
    const float* prow = P  + (size_t)t*NN*HD + b*HD;
    const float* vrow = Vb + (size_t)b*HD;
    const float* mrow = hmean + (size_t)tb*HD;
    const float* xrow = Hm + (size_t)si*NN*HD + b*HD;
    float pv[10], p2[10], v2[10], phm[10], hm2[10], phx[10], hx2[10];
    #pragma unroll
    for (int u = 0; u < 10; u++) {
        int h = lane + 32*u;
        float p  = (h < HD) ? prow[h] : 0.f;
        float v  = (h < HD) ? vrow[h] : 0.f;
        float hm = (h < HD) ? mrow[h] : 0.f;
        float hx = (h < HD) ? xrow[h] : 0.f;
        pv[u] = p*v;  p2[u] = p*p;   v2[u] = v*v;
        phm[u] = p*hm; hm2[u] = hm*hm;
        phx[u] = p*hx; hx2[u] = hx*hx;
    }
    for (int l = warp; l < LL; l += 4) {
        float nf = 0, pf = 0, vf = 0, na = 0, pa = 0, qa = 0, nm = 0, pm = 0, qm = 0;
        #pragma unroll
        for (int u = 0; u < 10; u++) {
            int h = lane + 32*u;
            float wfv = (h < HD) ? Wf [l*HD + h] : 0.f; float wf2 = wfv*wfv;
            float wav = (h < HD) ? Wa [l*HD + h] : 0.f; float wa2 = wav*wav;
            float wmv = (h < HD) ? Wma[l*HD + h] : 0.f; float wm2 = wmv*wmv;
            nf += pv[u]*wf2;  pf += p2[u]*wf2;  vf += v2[u]*wf2;
            na += phm[u]*wa2; pa += p2[u]*wa2;  qa += hm2[u]*wa2;
            nm += phx[u]*wm2; pm += p2[u]*wm2;  qm += hx2[u]*wm2;
        }
        for (int o = 16; o; o >>= 1) {
            nf += __shfl_down_sync(0xffffffffu, nf, o);
            pf += __shfl_down_sync(0xffffffffu, pf, o);
            vf += __shfl_down_sync(0xffffffffu, vf, o);
            na += __shfl_down_sync(0xffffffffu, na, o);
            pa += __shfl_down_sync(0xffffffffu, pa, o);
            qa += __shfl_down_sync(0xffffffffu, qa, o);
            nm += __shfl_down_sync(0xffffffffu, nm, o);
            pm += __shfl_down_sync(0xffffffffu, pm, o);
            qm += __shfl_down_sync(0xffffffffu, qm, o);
        }
        if (lane == 0) {
            size_t base = (size_t)tb*ML + moff;
            mout[base + l]      = nf / (sqrtf(pf)*sqrtf(vf) + EPSF);
            mout[base + 40 + l] = na / (sqrtf(pa)*sqrtf(qa) + EPSF);
            mout[base + 60 + l] = nm / (sqrtf(pm)*sqrtf(qm) + EPSF);
        }
    }
}

// y = [relu]( bn(x) @ W^T + b ),  bn applied to the input row. One row per block.
__global__ void fc_kernel(const float* __restrict__ xa, const float* __restrict__ xb,
                          int Kin,
                          const float* __restrict__ W, const float* __restrict__ bias,
                          const float* __restrict__ gamma, const float* __restrict__ beta,
                          float inv,
                          float* __restrict__ y, int Co, int relu)
{
    __shared__ float sx[600];
    int r = blockIdx.x;
    int half = Kin / 2;
    for (int k = threadIdx.x; k < Kin; k += blockDim.x) {
        float xv;
        if (xb) xv = (k < half) ? xa[r*half + k] : xb[r*half + k - half];
        else    xv = xa[r*Kin + k];
        sx[k] = gamma[k]*xv*inv + beta[k];
    }
    __syncthreads();
    for (int c = threadIdx.x; c < Co; c += blockDim.x) {
        float a = bias[c];
        for (int k = 0; k < Kin; k++) a += sx[k] * W[(size_t)c*Kin + k];
        y[r*Co + c] = (relu && a < 0.f) ? 0.f : a;
    }
}

// ---------------- host orchestration ----------------

static void run_mp(const float* P, const float* Hm, const float* Vb,
                   const float* Wf, const float* Wm, const float* Wa, const float* Wma,
                   float* mbuf, int moff,
                   float* Pl2, float* Hl2, float* wbuf, int* idxb,
                   float* hmean, float* pnm, float* hnm)
{
    l2_kernel   <<<TT*BB, 64>>>(P, Hm, Pl2, Hl2);
    att_kernel  <<<BB, 256>>>(P, Hm, Pl2, Hl2, wbuf, idxb);
    hmean_kernel<<<BB, 256>>>(Hm, wbuf, hmean);
    pnhn_kernel <<<TT*BB, 128>>>(P, Hm, Wm, pnm, hnm);
    maxp_3tf32_kernel<<<BB, 128, MAXP_SMEM_FLOATS*4>>>(P, Hm, Wm, pnm, hnm, mbuf, moff);
    mpcomb_kernel<<<TT*BB, 128>>>(P, Hm, Vb, hmean, idxb, Wf, Wa, Wma, mbuf, moff);
}

extern "C" void kernel_launch(void* const* d_in, const int* in_sizes, int n_in,
                              void* d_out, int out_size)
{
    const int*   premise    = (const int*)d_in[0];
    const int*   hypothesis = (const int*)d_in[1];
    const float* embed_W    = (const float*)d_in[2];
    const float* cell_Wih   = (const float*)d_in[3];
    const float* cell_Whh   = (const float*)d_in[4];
    const float* cell_b     = (const float*)d_in[5];
    const float* mp_W       = (const float*)d_in[6];
    const float* agg_Wih_f  = (const float*)d_in[7];
    const float* agg_Whh_f  = (const float*)d_in[8];
    const float* agg_b_f    = (const float*)d_in[9];
    const float* agg_Wih_b  = (const float*)d_in[10];
    const float* agg_Whh_b  = (const float*)d_in[11];
    const float* agg_b_b    = (const float*)d_in[12];
    const float* bn_gamma   = (const float*)d_in[13];
    const float* bn_beta    = (const float*)d_in[14];
    const float* mlp_W1     = (const float*)d_in[15];
    const float* mlp_b1     = (const float*)d_in[16];
    const float* mlp_W2     = (const float*)d_in[17];
    const float* mlp_b2     = (const float*)d_in[18];
    const float* out_W      = (const float*)d_in[19];
    const float* out_b      = (const float*)d_in[20];
    float* outp = (float*)d_out;

    float *comb, *Xg, *hsf, *hsb, *cf, *cb, *mbuf, *aXf, *aXb;
    float *ahf, *ahb, *acf, *acb, *wbuf, *Pl2, *Hl2, *hmean, *pnm, *hnm, *y1, *y2;
    int *idxb;
    cudaGetSymbolAddress((void**)&comb, g_comb);
    cudaGetSymbolAddress((void**)&Xg,   g_Xg);
    cudaGetSymbolAddress((void**)&hsf,  g_hsf);
    cudaGetSymbolAddress((void**)&hsb,  g_hsb);
    cudaGetSymbolAddress((void**)&cf,   g_cf);
    cudaGetSymbolAddress((void**)&cb,   g_cb);
    cudaGetSymbolAddress((void**)&mbuf, g_m);
    cudaGetSymbolAddress((void**)&aXf,  g_aXf);
    cudaGetSymbolAddress((void**)&aXb,  g_aXb);
    cudaGetSymbolAddress((void**)&ahf,  g_ahf);
    cudaGetSymbolAddress((void**)&ahb,  g_ahb);
    cudaGetSymbolAddress((void**)&acf,  g_acf);
    cudaGetSymbolAddress((void**)&acb,  g_acb);
    cudaGetSymbolAddress((void**)&wbuf, g_w);
    cudaGetSymbolAddress((void**)&idxb, g_idx);
    cudaGetSymbolAddress((void**)&Pl2,  g_Pl2);
    cudaGetSymbolAddress((void**)&Hl2,  g_Hl2);
    cudaGetSymbolAddress((void**)&hmean,g_hmean);
    cudaGetSymbolAddress((void**)&pnm,  g_pnm);
    cudaGetSymbolAddress((void**)&hnm,  g_hnm);
    cudaGetSymbolAddress((void**)&y1,   g_y1);
    cudaGetSymbolAddress((void**)&y2,   g_y2);

    // allow big dynamic smem for maxp (idempotent; not a stream op)
    cudaFuncSetAttribute(maxp_3tf32_kernel,
                         cudaFuncAttributeMaxDynamicSharedMemorySize, MAXP_SMEM_FLOATS*4);

    // 1. embedding gather -> comb (T,256,300)
    embed_kernel<<<(TT*NN*DD + 255)/256, 256>>>(premise, hypothesis, embed_W, comb);

    // 2. input projection for LSTM1, all timesteps at once (3xTF32 tensor cores)
    gemm_nt_3tf32<<<dim3(19, 256), 128>>>(comb, cell_Wih, cell_b, Xg, TT*NN, GG, DD);

    // 3. BiLSTM1 recurrence (64 steps; both directions per launch) - fp32
    const int TS = NN*HD;
    for (int s = 0; s < 64; s++) {
        int first = (s == 0);
        const float* hpf = first ? nullptr : hsf + (size_t)(s - 1)*TS;
        const float* hpb = first ? nullptr : hsb + (size_t)(64 - s)*TS;
        lstm_step2<64><<<dim3(19, 4, 2), dim3(16, 16)>>>(
            Xg + (size_t)s*NN*GG, Xg + (size_t)(63 - s)*NN*GG,
            cell_Whh, cell_Whh,
            hpf, hpb,
            hsf + (size_t)s*TS, hsb + (size_t)(63 - s)*TS,
            cf, cb, first);
    }

    // 4. multi-perspective matching (4 invocations -> m (T,128,320))
    run_mp(hsf, hsf + BB*HD, hsf + (size_t)63*TS + BB*HD,
           mp_W + 0, mp_W + 6000, mp_W + 12000, mp_W + 18000,
           mbuf, 0, Pl2, Hl2, wbuf, idxb, hmean, pnm, hnm);
    run_mp(hsb, hsb + BB*HD, hsb + BB*HD,
           mp_W + 24000, mp_W + 30000, mp_W + 36000, mp_W + 42000,
           mbuf, 80, Pl2, Hl2, wbuf, idxb, hmean, pnm, hnm);
    run_mp(hsf + BB*HD, hsf, hsf + (size_t)63*TS,
           mp_W + 0, mp_W + 6000, mp_W + 12000, mp_W + 18000,
           mbuf, 160, Pl2, Hl2, wbuf, idxb, hmean, pnm, hnm);
    run_mp(hsb + BB*HD, hsb, hsb,
           mp_W + 24000, mp_W + 30000, mp_W + 36000, mp_W + 42000,
           mbuf, 240, Pl2, Hl2, wbuf, idxb, hmean, pnm, hnm);

    // 5. aggregation input projections (3xTF32 tensor cores)
    gemm_nt_3tf32<<<dim3(19, 128), 128>>>(mbuf, agg_Wih_f, agg_b_f, aXf, TT*BB, GG, ML);
    gemm_nt_3tf32<<<dim3(19, 128), 128>>>(mbuf, agg_Wih_b, agg_b_b, aXb, TT*BB, GG, ML);

    // 6. aggregation BiLSTM (need only final hidden states; double-buffered h)
    for (int s = 0; s < 64; s++) {
        int first = (s == 0);
        int pi = s & 1, po = (s + 1) & 1;
        lstm_step2<32><<<dim3(19, 4, 2), dim3(16, 8)>>>(
            aXf + (size_t)s*BB*GG, aXb + (size_t)(63 - s)*BB*GG,
            agg_Whh_f, agg_Whh_b,
            first ? nullptr : ahf + pi*BB*HD, first ? nullptr : ahb + pi*BB*HD,
            ahf + po*BB*HD, ahb + po*BB*HD,
            acf, acb, first);
    }
    const float* af = ahf;
    const float* ab = ahb;

    // 7. head: bn -> fc -> relu (x2) -> bn -> out
    float inv = (float)(1.0 / sqrt(1.0 + 1e-5));
    fc_kernel<<<BB, 256>>>(af, ab, 600, mlp_W1, mlp_b1, bn_gamma,        bn_beta,        inv, y1, 600, 1);
    fc_kernel<<<BB, 256>>>(y1, nullptr, 600, mlp_W2, mlp_b2, bn_gamma + 600,  bn_beta + 600,  inv, y2, 600, 1);
    fc_kernel<<<BB, 256>>>(y2, nullptr, 600, out_W,  out_b,  bn_gamma + 1200, bn_beta + 1200, inv, outp, 3, 0);
}